// round 15
// baseline (speedup 1.0000x reference)
#include <cuda_runtime.h>
#include <cuda_bf16.h>
#include <cstdint>

#define NROWS 16384
#define BDIM  8192
#define DDIM  128
#define THREADS 256
#define SM_A    0
#define SM_B    32768
#define SM_RED  65536
#define SM_TOTAL (65536 + 8192)   // A32K + B32K + 8K scratch -> 2 CTAs/SM
#define FFMA_Q0 1
#define FFMA_Q1 20                // q in [1,20] -> FFMA path (1280 tiles)

// allocation-free scratch
__device__ float  g_denom[NROWS];
__device__ float  g_sppos[NROWS];
__device__ double g_total;
__device__ unsigned int g_count;
__device__ __nv_bfloat16 g_z[NROWS * DDIM];   // 4 MB, L2-resident

// ---------------- helpers ----------------
__device__ __forceinline__ uint32_t smem_u32(const void* p) {
    uint32_t a;
    asm("{ .reg .u64 t; cvta.to.shared.u64 t, %1; cvt.u32.u64 %0, t; }" : "=r"(a) : "l"(p));
    return a;
}
#define LDSM4(r, addr) \
    asm volatile("ldmatrix.sync.aligned.m8n8.x4.shared.b16 {%0,%1,%2,%3}, [%4];" \
        : "=r"((r)[0]), "=r"((r)[1]), "=r"((r)[2]), "=r"((r)[3]) : "r"(addr))
#define MMA16816(d, a, b0, b1) \
    asm volatile("mma.sync.aligned.m16n8k16.row.col.f32.bf16.bf16.f32 " \
        "{%0,%1,%2,%3}, {%4,%5,%6,%7}, {%8,%9}, {%0,%1,%2,%3};" \
        : "+f"((d)[0]), "+f"((d)[1]), "+f"((d)[2]), "+f"((d)[3]) \
        : "r"((a)[0]), "r"((a)[1]), "r"((a)[2]), "r"((a)[3]), "r"(b0), "r"(b1))
#define LDS128(r, addr) \
    asm volatile("ld.shared.v4.u32 {%0,%1,%2,%3}, [%4];" \
        : "=r"((r)[0]), "=r"((r)[1]), "=r"((r)[2]), "=r"((r)[3]) : "r"(addr))

// packed f32x2 (R1-proven on this harness)
__device__ __forceinline__ void ffma2(uint64_t& d, uint64_t a, uint64_t b) {
    asm("fma.rn.f32x2 %0, %1, %2, %0;" : "+l"(d) : "l"(a), "l"(b));
}
// u32 holds {bf16 k1 (hi), bf16 k0 (lo)} -> f32x2 {fp32(k0), fp32(k1)}
// raw: hi lane keeps garbage low-mantissa bits (<=2^-8 rel; ok for denominators)
__device__ __forceinline__ uint64_t bfpair_raw(uint32_t u) {
    uint64_t p; uint32_t lo = u << 16;
    asm("mov.b64 %0, {%1, %2};" : "=l"(p) : "r"(lo), "r"(u));
    return p;
}
__device__ __forceinline__ uint64_t bfpair_exact(uint32_t u) {
    uint64_t p; uint32_t lo = u << 16; uint32_t hi = u & 0xffff0000u;
    asm("mov.b64 %0, {%1, %2};" : "=l"(p) : "r"(lo), "r"(hi));
    return p;
}
__device__ __forceinline__ float2 upk2(uint64_t p) {
    float2 r;
    asm("mov.b64 {%0, %1}, %2;" : "=f"(r.x), "=f"(r.y) : "l"(p));
    return r;
}

// 128x128 bf16 tile: smem row = 256B, 16B chunk c stored at c ^ (row & 7)
__device__ __forceinline__ void load_tile_async(uint32_t sdst, const __nv_bfloat16* gsrc, int tid) {
    #pragma unroll
    for (int it = 0; it < 8; it++) {
        int i = tid + it * THREADS;          // 0..2047
        int row = i >> 4, c = i & 15;
        uint32_t dst = sdst + (uint32_t)(row * 256 + ((c ^ (row & 7)) * 16));
        const void* src = gsrc + (size_t)row * DDIM + c * 8;
        asm volatile("cp.async.cg.shared.global [%0], [%1], 16;" :: "r"(dst), "l"(src));
    }
}
#define CP_COMMIT() asm volatile("cp.async.commit_group;" ::: "memory")
#define CP_WAIT0()  asm volatile("cp.async.wait_group 0;" ::: "memory")

__device__ __forceinline__ float softplus2(float v) {   // softplus(2v), stable
    float x = v + v;
    float e;
    asm("ex2.approx.ftz.f32 %0, %1;" : "=f"(e) : "f"(v * 2.8853900817779268f));
    float l;
    asm("lg2.approx.ftz.f32 %0, %1;" : "=f"(l) : "f"(1.0f + e));
    float sp  = 0.6931471805599453f * l;
    float spn = __fmaf_rn(-0.5f * e, e, e);             // x << 0: e^x - e^2x/2
    sp = (x < -9.0f) ? spn : sp;
    sp = (x > 15.0f) ? x : sp;
    return sp;
}

// ---------------- convert + init (merged) ----------------
__global__ void convert_kernel(const float* __restrict__ za, const float* __restrict__ zb) {
    int i4 = blockIdx.x * blockDim.x + threadIdx.x;
    if (i4 < NROWS) g_denom[i4] = 0.0f;
    if (i4 == 0) { g_total = 0.0; g_count = 0u; }
    if (i4 >= NROWS * DDIM / 4) return;
    float4 v = (i4 < BDIM * DDIM / 4) ? ((const float4*)za)[i4]
                                      : ((const float4*)zb)[i4 - BDIM * DDIM / 4];
    ((__nv_bfloat162*)g_z)[i4 * 2]     = __nv_bfloat162(__float2bfloat16(v.x), __float2bfloat16(v.y));
    ((__nv_bfloat162*)g_z)[i4 * 2 + 1] = __nv_bfloat162(__float2bfloat16(v.z), __float2bfloat16(v.w));
}

// ---------------- tensor tile (R6-proven body) ----------------
template<bool DIAG, bool POS>
__device__ __forceinline__ void tile_work(int bi, int bj, char* smem, uint32_t sbase, int tid) {
    const int lane   = tid & 31;
    const int wid    = tid >> 5;
    const int warp_m = wid & 3;            // 4 row blocks of 32
    const int warp_n = wid >> 2;           // 2 col blocks of 64

    load_tile_async(sbase + SM_A, g_z + (size_t)bi * 128 * DDIM, tid);
    load_tile_async(sbase + SM_B, g_z + (size_t)bj * 128 * DDIM, tid);
    CP_COMMIT(); CP_WAIT0();
    __syncthreads();

    const int a_row = warp_m * 32 + (lane & 7) + ((lane >> 3) & 1) * 8;
    const int a_kc  = lane >> 4;
    const int b_row = warp_n * 64 + (lane & 7) + ((lane >> 4) & 1) * 8;
    const int b_kc  = (lane >> 3) & 1;

    float acc[2][8][4];
    #pragma unroll
    for (int mt = 0; mt < 2; mt++)
        #pragma unroll
        for (int nl = 0; nl < 8; nl++)
            #pragma unroll
            for (int i = 0; i < 4; i++) acc[mt][nl][i] = 0.f;

    #pragma unroll
    for (int ks = 0; ks < 8; ks++) {
        uint32_t a[2][4], b[4][4];
        #pragma unroll
        for (int mt = 0; mt < 2; mt++) {
            int row = a_row + mt * 16;
            int ch  = (ks * 2 + a_kc) ^ (row & 7);
            LDSM4(a[mt], sbase + SM_A + (uint32_t)(row * 256 + ch * 16));
        }
        #pragma unroll
        for (int g = 0; g < 4; g++) {
            int row = b_row + g * 16;
            int ch  = (ks * 2 + b_kc) ^ (row & 7);
            LDSM4(b[g], sbase + SM_B + (uint32_t)(row * 256 + ch * 16));
        }
        #pragma unroll
        for (int mt = 0; mt < 2; mt++)
            #pragma unroll
            for (int nl = 0; nl < 8; nl++)
                MMA16816(acc[mt][nl], a[mt], b[nl >> 1][(nl & 1) * 2], b[nl >> 1][(nl & 1) * 2 + 1]);
    }

    float rsum[2][2] = {{0.f, 0.f}, {0.f, 0.f}};
    float csum[16];
    #pragma unroll
    for (int c = 0; c < 16; c++) csum[c] = 0.f;

    #pragma unroll
    for (int mt = 0; mt < 2; mt++)
        #pragma unroll
        for (int nl = 0; nl < 8; nl++)
            #pragma unroll
            for (int i = 0; i < 4; i++) {
                float sp = softplus2(acc[mt][nl][i]);
                if (DIAG || POS) {
                    const int lr = warp_m * 32 + mt * 16 + (lane >> 2) + (i >> 1) * 8;
                    const int lc = warp_n * 64 + nl * 8 + (lane & 3) * 2 + (i & 1);
                    if (lr == lc) {
                        if (DIAG) sp = 0.0f;
                        else {
                            g_sppos[bi * 128 + lr] = sp;
                            g_sppos[bj * 128 + lc] = sp;
                        }
                    }
                }
                rsum[mt][i >> 1] += sp;
                csum[nl * 2 + (i & 1)] += sp;
            }

    float* srow = (float*)(smem + SM_RED);          // [2][128]
    float* scol = (float*)(smem + SM_RED + 1024);   // [4][128]
    #pragma unroll
    for (int mt = 0; mt < 2; mt++)
        #pragma unroll
        for (int h = 0; h < 2; h++) {
            float v = rsum[mt][h];
            v += __shfl_xor_sync(0xffffffffu, v, 1);
            v += __shfl_xor_sync(0xffffffffu, v, 2);
            if ((lane & 3) == 0)
                srow[warp_n * 128 + warp_m * 32 + mt * 16 + (lane >> 2) + h * 8] = v;
        }
    if (!DIAG) {
        #pragma unroll
        for (int c = 0; c < 16; c++) {
            float v = csum[c];
            v += __shfl_xor_sync(0xffffffffu, v, 4);
            v += __shfl_xor_sync(0xffffffffu, v, 8);
            v += __shfl_xor_sync(0xffffffffu, v, 16);
            if (lane < 4)
                scol[warp_m * 128 + warp_n * 64 + (c >> 1) * 8 + lane * 2 + (c & 1)] = v;
        }
    }
    __syncthreads();
    if (tid < 128) {
        float rt = srow[tid] + srow[128 + tid];
        atomicAdd(&g_denom[bi * 128 + tid], rt);
        if (!DIAG) {
            float ct = scol[tid] + scol[128 + tid] + scol[256 + tid] + scol[384 + tid];
            atomicAdd(&g_denom[bj * 128 + tid], ct);
        }
    }
}

// ---------------- FFMA tile (fma-pipe offload; never diag/pos) ----------------
__device__ __forceinline__ void ffma_tile_work(int bi, int bj, char* smem, uint32_t sbase, int tid) {
    const int tx = tid & 15;               // 16 col threads
    const int ty = tid >> 4;               // 16 row threads (rows ty*8..+7)

    load_tile_async(sbase + SM_A, g_z + (size_t)bi * 128 * DDIM, tid);
    load_tile_async(sbase + SM_B, g_z + (size_t)bj * 128 * DDIM, tid);
    CP_COMMIT(); CP_WAIT0();
    __syncthreads();

    float rsumf[8];
    #pragma unroll
    for (int r = 0; r < 8; r++) rsumf[r] = 0.f;
    float* scol = (float*)(smem + SM_RED);     // [16][128]

    #pragma unroll
    for (int pass = 0; pass < 2; pass++) {
        // thread cols this pass: (pass*4 + c)*16 + tx, c = 0..3
        uint64_t acc[8][4];                // [row][col], lanes = {k-even, k-odd} partial sums
        #pragma unroll
        for (int r = 0; r < 8; r++)
            #pragma unroll
            for (int c = 0; c < 4; c++) acc[r][c] = 0ull;

        #pragma unroll
        for (int kc = 0; kc < 16; kc++) {  // 16B chunk = 8 k values = 4 k-pairs
            uint64_t bp[4][4];             // [col][kpair]
            #pragma unroll
            for (int c = 0; c < 4; c++) {
                int brow = (pass * 4 + c) * 16 + tx;
                uint32_t bu[4];
                LDS128(bu, sbase + SM_B + (uint32_t)(brow * 256 + ((kc ^ (brow & 7)) * 16)));
                #pragma unroll
                for (int kp = 0; kp < 4; kp++) bp[c][kp] = bfpair_exact(bu[kp]);
            }
            #pragma unroll
            for (int r = 0; r < 8; r++) {
                int arow = ty * 8 + r;
                uint32_t au[4];
                LDS128(au, sbase + SM_A + (uint32_t)(arow * 256 + ((kc ^ (arow & 7)) * 16)));
                #pragma unroll
                for (int kp = 0; kp < 4; kp++) {
                    uint64_t ap = bfpair_raw(au[kp]);
                    #pragma unroll
                    for (int c = 0; c < 4; c++) ffma2(acc[r][c], ap, bp[c][kp]);
                }
            }
        }

        // epilogue for this pass
        #pragma unroll
        for (int c = 0; c < 4; c++) {
            float colp = 0.f;
            #pragma unroll
            for (int r = 0; r < 8; r++) {
                float2 h = upk2(acc[r][c]);
                float sp = softplus2(h.x + h.y);
                rsumf[r] += sp;
                colp += sp;
            }
            scol[ty * 128 + (pass * 4 + c) * 16 + tx] = colp;
        }
    }

    // row sums: reduce across the 16 tx threads (lane bits 0..3)
    #pragma unroll
    for (int r = 0; r < 8; r++) {
        float v = rsumf[r];
        v += __shfl_xor_sync(0xffffffffu, v, 1);
        v += __shfl_xor_sync(0xffffffffu, v, 2);
        v += __shfl_xor_sync(0xffffffffu, v, 4);
        v += __shfl_xor_sync(0xffffffffu, v, 8);
        if (tx == 0) atomicAdd(&g_denom[bi * 128 + ty * 8 + r], v);
    }
    // col sums: 16 ty partials per column
    __syncthreads();
    if (tid < 128) {
        float s = 0.f;
        #pragma unroll
        for (int t = 0; t < 16; t++) s += scol[t * 128 + tid];
        atomicAdd(&g_denom[bj * 128 + tid], s);
    }
}

__global__ __launch_bounds__(THREADS, 2)
void fused_tri_kernel() {
    // exact rectangle -> upper-triangle map: 129 x 64 = 8256 CTAs, zero waste
    const int p = blockIdx.y;              // 0..63
    const int q = blockIdx.x;              // 0..128
    extern __shared__ char smem[];
    const uint32_t sbase = smem_u32(smem);

    if (q >= FFMA_Q0 && q <= FFMA_Q1) {    // FFMA region: no diag, no pos, no fold
        ffma_tile_work(p, p + q, smem, sbase, threadIdx.x);
        return;
    }
    int bi = p, bj = p + q;
    if (bj >= 128) { bi = 127 - p; bj = q - 1; }
    if (bi == bj)              tile_work<true,  false>(bi, bj, smem, sbase, threadIdx.x);
    else if (bj == (bi ^ 64))  tile_work<false, true >(bi, bj, smem, sbase, threadIdx.x);
    else                       tile_work<false, false>(bi, bj, smem, sbase, threadIdx.x);
}

// ---------------- parallel finalize (last block writes out) ----------------
__global__ void finalize_part(float* __restrict__ out) {
    __shared__ double red[256];
    const int i = blockIdx.x * 256 + threadIdx.x;     // 64*256 == NROWS exactly
    float spp = fmaxf(g_sppos[i], 1e-8f);
    float den = fmaxf(g_denom[i], 1e-8f);
    red[threadIdx.x] = (double)(logf(spp) - logf(den));
    __syncthreads();
    for (int o = 128; o > 0; o >>= 1) {
        if (threadIdx.x < o) red[threadIdx.x] += red[threadIdx.x + o];
        __syncthreads();
    }
    if (threadIdx.x == 0) {
        atomicAdd(&g_total, red[0]);
        __threadfence();
        unsigned int done = atomicAdd(&g_count, 1u);
        if (done == 63u) {
            __threadfence();
            double tot = *((volatile double*)&g_total);
            out[0] = (float)(-tot / (double)NROWS);
        }
    }
}

extern "C" void kernel_launch(void* const* d_in, const int* in_sizes, int n_in,
                              void* d_out, int out_size) {
    const float* za = (const float*)d_in[0];
    const float* zb = (const float*)d_in[1];
    float* out = (float*)d_out;

    cudaFuncSetAttribute(fused_tri_kernel, cudaFuncAttributeMaxDynamicSharedMemorySize, SM_TOTAL);

    convert_kernel<<<(NROWS * DDIM / 4 + 255) / 256, 256>>>(za, zb);
    dim3 grid(129, 64);                   // exact triangular cover
    fused_tri_kernel<<<grid, THREADS, SM_TOTAL>>>();
    finalize_part<<<64, 256>>>(out);
}

// round 17
// speedup vs baseline: 2.4418x; 2.4418x over previous
#include <cuda_runtime.h>
#include <cuda_bf16.h>
#include <cstdint>

#define NROWS 16384
#define BDIM  8192
#define DDIM  128
#define THREADS 256
#define SM_A   0
#define SM_B   32768
#define SM_TOTAL 65536        // 64 KB -> 2 CTAs/SM

// allocation-free scratch
__device__ float  g_denom[NROWS];
__device__ float  g_sppos[NROWS];
__device__ double g_total;
__device__ unsigned int g_count;
__device__ __nv_bfloat16 g_z[NROWS * DDIM];   // 4 MB, L2-resident

// ---------------- helpers ----------------
__device__ __forceinline__ uint32_t smem_u32(const void* p) {
    uint32_t a;
    asm("{ .reg .u64 t; cvta.to.shared.u64 t, %1; cvt.u32.u64 %0, t; }" : "=r"(a) : "l"(p));
    return a;
}
#define LDSM4(r, addr) \
    asm volatile("ldmatrix.sync.aligned.m8n8.x4.shared.b16 {%0,%1,%2,%3}, [%4];" \
        : "=r"((r)[0]), "=r"((r)[1]), "=r"((r)[2]), "=r"((r)[3]) : "r"(addr))
#define MMA16816(d, a, b0, b1) \
    asm volatile("mma.sync.aligned.m16n8k16.row.col.f32.bf16.bf16.f32 " \
        "{%0,%1,%2,%3}, {%4,%5,%6,%7}, {%8,%9}, {%0,%1,%2,%3};" \
        : "+f"((d)[0]), "+f"((d)[1]), "+f"((d)[2]), "+f"((d)[3]) \
        : "r"((a)[0]), "r"((a)[1]), "r"((a)[2]), "r"((a)[3]), "r"(b0), "r"(b1))

// 128x128 bf16 tile: smem row = 256B, 16B chunk c stored at c ^ (row & 7)
__device__ __forceinline__ void load_tile_async(uint32_t sdst, const __nv_bfloat16* gsrc, int tid) {
    #pragma unroll
    for (int it = 0; it < 8; it++) {
        int i = tid + it * THREADS;          // 0..2047
        int row = i >> 4, c = i & 15;
        uint32_t dst = sdst + (uint32_t)(row * 256 + ((c ^ (row & 7)) * 16));
        const void* src = gsrc + (size_t)row * DDIM + c * 8;
        asm volatile("cp.async.cg.shared.global [%0], [%1], 16;" :: "r"(dst), "l"(src));
    }
}
#define CP_COMMIT() asm volatile("cp.async.commit_group;" ::: "memory")
#define CP_WAIT0()  asm volatile("cp.async.wait_group 0;" ::: "memory")

// ---------------- convert + init (merged) ----------------
__global__ void convert_kernel(const float* __restrict__ za, const float* __restrict__ zb) {
    int i4 = blockIdx.x * blockDim.x + threadIdx.x;
    if (i4 < NROWS) g_denom[i4] = 0.0f;
    if (i4 == 0) { g_total = 0.0; g_count = 0u; }
    if (i4 >= NROWS * DDIM / 4) return;
    float4 v = (i4 < BDIM * DDIM / 4) ? ((const float4*)za)[i4]
                                      : ((const float4*)zb)[i4 - BDIM * DDIM / 4];
    ((__nv_bfloat162*)g_z)[i4 * 2]     = __nv_bfloat162(__float2bfloat16(v.x), __float2bfloat16(v.y));
    ((__nv_bfloat162*)g_z)[i4 * 2 + 1] = __nv_bfloat162(__float2bfloat16(v.z), __float2bfloat16(v.w));
}

// ---------------- fused triangular kernel (144.0 us proven body) ----------------
template<bool DIAG, bool POS>
__device__ __forceinline__ void tile_work(int bi, int bj, char* smem, uint32_t sbase, int tid) {
    const int lane   = tid & 31;
    const int wid    = tid >> 5;
    const int warp_m = wid & 3;            // 4 row blocks of 32
    const int warp_n = wid >> 2;           // 2 col blocks of 64

    load_tile_async(sbase + SM_A, g_z + (size_t)bi * 128 * DDIM, tid);
    load_tile_async(sbase + SM_B, g_z + (size_t)bj * 128 * DDIM, tid);
    CP_COMMIT();
    CP_WAIT0();
    __syncthreads();

    const int a_row = warp_m * 32 + (lane & 7) + ((lane >> 3) & 1) * 8;   // + mt*16
    const int a_kc  = lane >> 4;
    const int b_row = warp_n * 64 + (lane & 7) + ((lane >> 4) & 1) * 8;   // + g*16
    const int b_kc  = (lane >> 3) & 1;

    float acc[2][8][4];
    #pragma unroll
    for (int mt = 0; mt < 2; mt++)
        #pragma unroll
        for (int nl = 0; nl < 8; nl++)
            #pragma unroll
            for (int i = 0; i < 4; i++) acc[mt][nl][i] = 0.f;

    #pragma unroll
    for (int ks = 0; ks < 8; ks++) {
        uint32_t a[2][4], b[4][4];
        #pragma unroll
        for (int mt = 0; mt < 2; mt++) {
            int row = a_row + mt * 16;
            int ch  = (ks * 2 + a_kc) ^ (row & 7);
            LDSM4(a[mt], sbase + SM_A + (uint32_t)(row * 256 + ch * 16));
        }
        #pragma unroll
        for (int g = 0; g < 4; g++) {
            int row = b_row + g * 16;
            int ch  = (ks * 2 + b_kc) ^ (row & 7);
            LDSM4(b[g], sbase + SM_B + (uint32_t)(row * 256 + ch * 16));
        }
        #pragma unroll
        for (int mt = 0; mt < 2; mt++)
            #pragma unroll
            for (int nl = 0; nl < 8; nl++)
                MMA16816(acc[mt][nl], a[mt], b[nl >> 1][(nl & 1) * 2], b[nl >> 1][(nl & 1) * 2 + 1]);
    }

    // ---- fused epilogue ----
    float rsum[2][2] = {{0.f, 0.f}, {0.f, 0.f}};
    float csum[16];
    #pragma unroll
    for (int c = 0; c < 16; c++) csum[c] = 0.f;

    #pragma unroll
    for (int mt = 0; mt < 2; mt++)
        #pragma unroll
        for (int nl = 0; nl < 8; nl++)
            #pragma unroll
            for (int i = 0; i < 4; i++) {
                float v = acc[mt][nl][i];
                float x = v + v;                          // sim / tau, tau = 0.5
                float e;
                asm("ex2.approx.ftz.f32 %0, %1;" : "=f"(e) : "f"(x * 1.4426950408889634f));
                float l;
                asm("lg2.approx.ftz.f32 %0, %1;" : "=f"(l) : "f"(1.0f + e));
                float sp  = 0.6931471805599453f * l;
                float spn = __fmaf_rn(-0.5f * e, e, e);   // x << 0: e^x - e^2x/2
                sp = (x < -9.0f) ? spn : sp;
                sp = (x > 15.0f) ? x : sp;
                if (DIAG || POS) {
                    const int lr = warp_m * 32 + mt * 16 + (lane >> 2) + (i >> 1) * 8;
                    const int lc = warp_n * 64 + nl * 8 + (lane & 3) * 2 + (i & 1);
                    if (DIAG) { if (lr == lc) sp = 0.0f; }
                    if (POS)  { if (lr == lc) {            // global col == row ^ 8192 here
                        g_sppos[bi * 128 + lr] = sp;
                        g_sppos[bj * 128 + lc] = sp;
                    } }
                }
                rsum[mt][i >> 1] += sp;
                if (!DIAG) csum[nl * 2 + (i & 1)] += sp;
            }

    // ---- reductions (A/B smem dead now) ----
    __syncthreads();
    float* srow = (float*)(smem);          // [2(warp_n)][128]
    float* scol = (float*)(smem + 1024);   // [4(warp_m)][128]
    #pragma unroll
    for (int mt = 0; mt < 2; mt++)
        #pragma unroll
        for (int h = 0; h < 2; h++) {
            float v = rsum[mt][h];
            v += __shfl_xor_sync(0xffffffffu, v, 1);
            v += __shfl_xor_sync(0xffffffffu, v, 2);
            if ((lane & 3) == 0)
                srow[warp_n * 128 + warp_m * 32 + mt * 16 + (lane >> 2) + h * 8] = v;
        }
    if (!DIAG) {
        #pragma unroll
        for (int c = 0; c < 16; c++) {
            float v = csum[c];
            v += __shfl_xor_sync(0xffffffffu, v, 4);
            v += __shfl_xor_sync(0xffffffffu, v, 8);
            v += __shfl_xor_sync(0xffffffffu, v, 16);
            if (lane < 4)
                scol[warp_m * 128 + warp_n * 64 + (c >> 1) * 8 + lane * 2 + (c & 1)] = v;
        }
    }
    __syncthreads();
    if (tid < 128) {
        float rt = srow[tid] + srow[128 + tid];
        atomicAdd(&g_denom[bi * 128 + tid], rt);
        if (!DIAG) {
            float ct = scol[tid] + scol[128 + tid] + scol[256 + tid] + scol[384 + tid];
            atomicAdd(&g_denom[bj * 128 + tid], ct);
        }
    }
}

__global__ __launch_bounds__(THREADS, 2)
void fused_tri_kernel() {
    // exact rectangle -> upper-triangle map: 129 x 64 = 8256 CTAs, zero waste
    const int p = blockIdx.y;              // 0..63
    const int q = blockIdx.x;              // 0..128
    int bi = p, bj = p + q;
    if (bj >= 128) { bi = 127 - p; bj = q - 1; }
    extern __shared__ char smem[];
    const uint32_t sbase = smem_u32(smem);
    if (bi == bj)            tile_work<true,  false>(bi, bj, smem, sbase, threadIdx.x);
    else if (bj == (bi ^ 64))tile_work<false, true >(bi, bj, smem, sbase, threadIdx.x);
    else                     tile_work<false, false>(bi, bj, smem, sbase, threadIdx.x);
}

// ---------------- parallel finalize (fast log, last block writes out) ----------------
__global__ void finalize_part(float* __restrict__ out) {
    __shared__ double red[256];
    const int i = blockIdx.x * 256 + threadIdx.x;     // 64*256 == NROWS exactly
    float spp = fmaxf(g_sppos[i], 1e-8f);
    float den = fmaxf(g_denom[i], 1e-8f);
    // log(spp) - log(den) = ln2 * (lg2(spp) - lg2(den)); inputs far from denormals
    float l1, l2;
    asm("lg2.approx.ftz.f32 %0, %1;" : "=f"(l1) : "f"(spp));
    asm("lg2.approx.ftz.f32 %0, %1;" : "=f"(l2) : "f"(den));
    red[threadIdx.x] = (double)(0.6931471805599453f * (l1 - l2));
    __syncthreads();
    for (int o = 128; o > 0; o >>= 1) {
        if (threadIdx.x < o) red[threadIdx.x] += red[threadIdx.x + o];
        __syncthreads();
    }
    if (threadIdx.x == 0) {
        atomicAdd(&g_total, red[0]);
        __threadfence();
        unsigned int done = atomicAdd(&g_count, 1u);
        if (done == 63u) {                   // last block publishes the scalar
            __threadfence();
            double tot = *((volatile double*)&g_total);
            out[0] = (float)(-tot / (double)NROWS);
        }
    }
}

extern "C" void kernel_launch(void* const* d_in, const int* in_sizes, int n_in,
                              void* d_out, int out_size) {
    const float* za = (const float*)d_in[0];
    const float* zb = (const float*)d_in[1];
    float* out = (float*)d_out;

    cudaFuncSetAttribute(fused_tri_kernel, cudaFuncAttributeMaxDynamicSharedMemorySize, SM_TOTAL);

    convert_kernel<<<(NROWS * DDIM / 4 + 255) / 256, 256>>>(za, zb);
    dim3 grid(129, 64);                   // exact triangular cover
    fused_tri_kernel<<<grid, THREADS, SM_TOTAL>>>();
    finalize_part<<<64, 256>>>(out);
}